// round 1
// baseline (speedup 1.0000x reference)
#include <cuda_runtime.h>

#define B_   8192
#define D_   1024
#define H_   1024
#define E_   8
#define KC   5
#define KM1  4
#define EPS_ 1e-8f

// ---------------- scratch (device globals; no allocations allowed) ----------------
__device__ int   g_cnt[E_];
__device__ int   g_pos[E_];
__device__ int   g_off[E_ + 1];
__device__ int   g_tok[B_];          // gathered order -> original token id
__device__ int   g_is64;             // 1 if size_idx is int64
__device__ float g_h[(size_t)B_ * H_]; // 32 MB hidden activations (gathered order)

__device__ __forceinline__ int get_expert(const int* __restrict__ sidx, int b) {
    return g_is64 ? sidx[2 * b] : sidx[b];
}

// ---------------- routing ----------------
// Detect int32 vs int64 size_idx + zero counters. 1 block.
__global__ void k_detect(const int* __restrict__ sidx) {
    __shared__ int s_any;
    if (threadIdx.x == 0) s_any = 0;
    __syncthreads();
    int any = 0;
    // If int64: int32 view = [v0,0,v1,0,...] -> odd slots (within first 8192 ints) all zero.
    for (int i = threadIdx.x; i < B_ / 2; i += blockDim.x)
        if (sidx[2 * i + 1] != 0) any = 1;
    if (any) atomicOr(&s_any, 1);
    __syncthreads();
    if (threadIdx.x == 0) g_is64 = (s_any == 0) ? 1 : 0;
    for (int i = threadIdx.x; i < E_; i += blockDim.x) { g_cnt[i] = 0; g_pos[i] = 0; }
}

__global__ void k_count(const int* __restrict__ sidx) {
    int b = blockIdx.x * blockDim.x + threadIdx.x;
    if (b < B_) atomicAdd(&g_cnt[get_expert(sidx, b)], 1);
}

__global__ void k_scan() {
    if (threadIdx.x == 0) {
        int acc = 0;
        for (int e = 0; e < E_; e++) { g_off[e] = acc; acc += g_cnt[e]; }
        g_off[E_] = acc;
    }
}

__global__ void k_scatter(const int* __restrict__ sidx) {
    int b = blockIdx.x * blockDim.x + threadIdx.x;
    if (b < B_) {
        int e = get_expert(sidx, b);
        int p = g_off[e] + atomicAdd(&g_pos[e], 1);
        g_tok[p] = b;
    }
}

// ---------------- GEMM1: h = relu(Xg @ W1[e] + b1[e]) ----------------
// 128x128 tile, 256 threads, 8x8 per thread, K-chunk 16.
__global__ __launch_bounds__(256) void k_gemm1(const float* __restrict__ x,
                                               const float* __restrict__ W1,
                                               const float* __restrict__ b1) {
    const int e   = blockIdx.z;
    const int off = g_off[e];
    const int cnt = g_off[e + 1] - off;
    const int m0  = blockIdx.y * 128;
    if (m0 >= cnt) return;
    const int n0  = blockIdx.x * 128;

    __shared__ float As[16][132];   // [k][m], padded (2-way max conflict on store)
    __shared__ float Bs[16][128];   // [k][n]

    const int tid = threadIdx.x;
    const int tx  = tid & 15;       // n-dim thread coord
    const int ty  = tid >> 4;       // m-dim thread coord

    // A-load assignment: 2 rows, one float4 of k each
    const int lrow = tid >> 2;               // 0..63
    const int lk4  = (tid & 3) * 4;          // 0,4,8,12
    const int row0 = lrow;
    const int row1 = 64 + lrow;
    const int gr0  = off + min(m0 + row0, cnt - 1);
    const int gr1  = off + min(m0 + row1, cnt - 1);
    const float* xr0 = x + (size_t)g_tok[gr0] * D_;
    const float* xr1 = x + (size_t)g_tok[gr1] * D_;

    const float* Wb = W1 + (size_t)e * D_ * H_ + n0;

    float acc[8][8];
#pragma unroll
    for (int i = 0; i < 8; i++)
#pragma unroll
        for (int j = 0; j < 8; j++) acc[i][j] = 0.f;

    for (int kt = 0; kt < D_; kt += 16) {
        float4 a0 = *(const float4*)(xr0 + kt + lk4);
        float4 a1 = *(const float4*)(xr1 + kt + lk4);
        As[lk4 + 0][row0] = a0.x; As[lk4 + 1][row0] = a0.y;
        As[lk4 + 2][row0] = a0.z; As[lk4 + 3][row0] = a0.w;
        As[lk4 + 0][row1] = a1.x; As[lk4 + 1][row1] = a1.y;
        As[lk4 + 2][row1] = a1.z; As[lk4 + 3][row1] = a1.w;
#pragma unroll
        for (int it = 0; it < 2; it++) {
            int lin = it * 1024 + tid * 4;
            int kk  = lin >> 7;
            int nn  = lin & 127;
            *(float4*)&Bs[kk][nn] = *(const float4*)(Wb + (size_t)(kt + kk) * H_ + nn);
        }
        __syncthreads();
#pragma unroll
        for (int kk = 0; kk < 16; kk++) {
            float a[8], b[8];
            *(float4*)(a)     = *(const float4*)&As[kk][ty * 8];
            *(float4*)(a + 4) = *(const float4*)&As[kk][ty * 8 + 4];
            *(float4*)(b)     = *(const float4*)&Bs[kk][tx * 8];
            *(float4*)(b + 4) = *(const float4*)&Bs[kk][tx * 8 + 4];
#pragma unroll
            for (int i = 0; i < 8; i++)
#pragma unroll
                for (int j = 0; j < 8; j++) acc[i][j] += a[i] * b[j];
        }
        __syncthreads();
    }

    float bias[8];
    *(float4*)(bias)     = *(const float4*)(b1 + (size_t)e * H_ + n0 + tx * 8);
    *(float4*)(bias + 4) = *(const float4*)(b1 + (size_t)e * H_ + n0 + tx * 8 + 4);

#pragma unroll
    for (int i = 0; i < 8; i++) {
        int m = m0 + ty * 8 + i;
        if (m < cnt) {
            float* dst = g_h + (size_t)(off + m) * H_ + n0 + tx * 8;
            float4 v0, v1;
            v0.x = fmaxf(acc[i][0] + bias[0], 0.f);
            v0.y = fmaxf(acc[i][1] + bias[1], 0.f);
            v0.z = fmaxf(acc[i][2] + bias[2], 0.f);
            v0.w = fmaxf(acc[i][3] + bias[3], 0.f);
            v1.x = fmaxf(acc[i][4] + bias[4], 0.f);
            v1.y = fmaxf(acc[i][5] + bias[5], 0.f);
            v1.z = fmaxf(acc[i][6] + bias[6], 0.f);
            v1.w = fmaxf(acc[i][7] + bias[7], 0.f);
            *(float4*)(dst)     = v0;
            *(float4*)(dst + 4) = v1;
        }
    }
}

// ---------------- GEMM2 + ordinal epilogue ----------------
// One warp per gathered row.
__global__ __launch_bounds__(256) void k_gemm2(const int* __restrict__ sidx,
                                               const float* __restrict__ W2,
                                               const float* __restrict__ b2,
                                               float* __restrict__ out, int out_size) {
    int warp = (blockIdx.x * blockDim.x + threadIdx.x) >> 5;
    int lane = threadIdx.x & 31;
    if (warp >= B_) return;
    int tok = g_tok[warp];
    int e   = get_expert(sidx, tok);

    const float* hrow = g_h + (size_t)warp * H_;
    const float* w    = W2 + (size_t)e * H_ * KM1;

    float a0 = 0.f, a1 = 0.f, a2 = 0.f, a3 = 0.f;
    for (int d = lane; d < H_; d += 32) {
        float hv = hrow[d];
        float4 wv = *(const float4*)(w + (size_t)d * 4);
        a0 += hv * wv.x; a1 += hv * wv.y; a2 += hv * wv.z; a3 += hv * wv.w;
    }
#pragma unroll
    for (int o = 16; o > 0; o >>= 1) {
        a0 += __shfl_down_sync(0xffffffffu, a0, o);
        a1 += __shfl_down_sync(0xffffffffu, a1, o);
        a2 += __shfl_down_sync(0xffffffffu, a2, o);
        a3 += __shfl_down_sync(0xffffffffu, a3, o);
    }
    if (lane == 0) {
        float l[KM1];
        l[0] = a0 + b2[e * KM1 + 0];
        l[1] = a1 + b2[e * KM1 + 1];
        l[2] = a2 + b2[e * KM1 + 2];
        l[3] = a3 + b2[e * KM1 + 3];
        float q[KM1];
#pragma unroll
        for (int k = 0; k < KM1; k++) q[k] = 1.f / (1.f + expf(-l[k]));
        float p[KC];
        p[0] = 1.f - q[0];
        p[1] = q[0] - q[1];
        p[2] = q[1] - q[2];
        p[3] = q[2] - q[3];
        p[4] = q[3];
        float s = 0.f;
#pragma unroll
        for (int k = 0; k < KC; k++) { p[k] = fmaxf(p[k], EPS_); s += p[k]; }
        s = fmaxf(s, EPS_);
        float inv = 1.f / s;
#pragma unroll
        for (int k = 0; k < KC; k++) p[k] *= inv;

        if (out_size >= B_ * (KM1 + KC)) {
#pragma unroll
            for (int k = 0; k < KM1; k++) out[(size_t)tok * KM1 + k] = l[k];
#pragma unroll
            for (int k = 0; k < KC; k++)  out[(size_t)B_ * KM1 + (size_t)tok * KC + k] = p[k];
        } else if (out_size == B_ * KC) {
#pragma unroll
            for (int k = 0; k < KC; k++)  out[(size_t)tok * KC + k] = p[k];
        } else {
#pragma unroll
            for (int k = 0; k < KM1; k++) out[(size_t)tok * KM1 + k] = l[k];
        }
    }
}

// ---------------- launch ----------------
extern "C" void kernel_launch(void* const* d_in, const int* in_sizes, int n_in,
                              void* d_out, int out_size) {
    const float* x    = (const float*)d_in[0];
    const int*   sidx = (const int*)  d_in[1];
    const float* W1   = (const float*)d_in[2];
    const float* b1   = (const float*)d_in[3];
    const float* W2   = (const float*)d_in[4];
    const float* b2   = (const float*)d_in[5];
    float*       out  = (float*)d_out;

    k_detect<<<1, 256>>>(sidx);
    k_count<<<B_ / 256, 256>>>(sidx);
    k_scan<<<1, 32>>>();
    k_scatter<<<B_ / 256, 256>>>(sidx);
    k_gemm1<<<dim3(H_ / 128, B_ / 128, E_), 256>>>(x, W1, b1);
    k_gemm2<<<B_ * 32 / 256, 256>>>(sidx, W2, b2, out, out_size);
}

// round 3
// speedup vs baseline: 2.0206x; 2.0206x over previous
#include <cuda_runtime.h>
#include <cuda_bf16.h>
#include <cstdint>

#define B_   8192
#define D_   1024
#define H_   1024
#define E_   8
#define KC   5
#define KM1  4
#define EPS_ 1e-8f

// ---------------- PTX helpers (sm_80-era only; no tcgen05 on this toolchain path) ----------------
__device__ __forceinline__ uint32_t smem_u32(const void* p) {
    uint32_t a;
    asm("{ .reg .u64 t; cvta.to.shared.u64 t, %1; cvt.u32.u64 %0, t; }" : "=r"(a) : "l"(p));
    return a;
}
__device__ __forceinline__ void cp16(uint32_t saddr, const void* g) {
    asm volatile("cp.async.cg.shared.global [%0], [%1], 16;" :: "r"(saddr), "l"(g));
}
#define CP_COMMIT() asm volatile("cp.async.commit_group;" ::: "memory")
#define CP_WAIT(N)  asm volatile("cp.async.wait_group %0;" :: "n"(N) : "memory")

__device__ __forceinline__ void ldsm4(uint32_t& r0, uint32_t& r1, uint32_t& r2, uint32_t& r3,
                                      uint32_t addr) {
    asm volatile("ldmatrix.sync.aligned.m8n8.x4.shared.b16 {%0,%1,%2,%3}, [%4];"
                 : "=r"(r0), "=r"(r1), "=r"(r2), "=r"(r3) : "r"(addr));
}
__device__ __forceinline__ void mma16816(float* c, const uint32_t* a, const uint32_t* b) {
    asm volatile(
        "mma.sync.aligned.m16n8k16.row.col.f32.bf16.bf16.f32 "
        "{%0,%1,%2,%3},{%4,%5,%6,%7},{%8,%9},{%0,%1,%2,%3};"
        : "+f"(c[0]), "+f"(c[1]), "+f"(c[2]), "+f"(c[3])
        : "r"(a[0]), "r"(a[1]), "r"(a[2]), "r"(a[3]), "r"(b[0]), "r"(b[1]));
}

// ---------------- scratch ----------------
__device__ int   g_cnt[E_];
__device__ int   g_pos[E_];
__device__ int   g_off[E_ + 1];
__device__ int   g_tok[B_];
__device__ int   g_is64;
__device__ float g_h[(size_t)B_ * H_];                       // 32 MB
__device__ __nv_bfloat16 g_xh[(size_t)B_ * D_];              // gathered x hi
__device__ __nv_bfloat16 g_xl[(size_t)B_ * D_];              // gathered x lo
__device__ __nv_bfloat16 g_wh[(size_t)E_ * H_ * D_];         // W1^T hi [e][n][k]
__device__ __nv_bfloat16 g_wl[(size_t)E_ * H_ * D_];         // W1^T lo

__device__ __forceinline__ int get_expert(const int* __restrict__ sidx, int b) {
    return g_is64 ? sidx[2 * b] : sidx[b];
}

// ---------------- routing ----------------
__global__ void k_detect(const int* __restrict__ sidx) {
    __shared__ int s_any;
    if (threadIdx.x == 0) s_any = 0;
    __syncthreads();
    int any = 0;
    for (int i = threadIdx.x; i < B_ / 2; i += blockDim.x)
        if (sidx[2 * i + 1] != 0) any = 1;
    if (any) atomicOr(&s_any, 1);
    __syncthreads();
    if (threadIdx.x == 0) g_is64 = (s_any == 0) ? 1 : 0;
    for (int i = threadIdx.x; i < E_; i += blockDim.x) { g_cnt[i] = 0; g_pos[i] = 0; }
}
__global__ void k_count(const int* __restrict__ sidx) {
    int b = blockIdx.x * blockDim.x + threadIdx.x;
    if (b < B_) atomicAdd(&g_cnt[get_expert(sidx, b)], 1);
}
__global__ void k_scan() {
    if (threadIdx.x == 0) {
        int acc = 0;
        for (int e = 0; e < E_; e++) { g_off[e] = acc; acc += g_cnt[e]; }
        g_off[E_] = acc;
    }
}
__global__ void k_scatter(const int* __restrict__ sidx) {
    int b = blockIdx.x * blockDim.x + threadIdx.x;
    if (b < B_) {
        int e = get_expert(sidx, b);
        int p = g_off[e] + atomicAdd(&g_pos[e], 1);
        g_tok[p] = b;
    }
}

// ---------------- conversions ----------------
__global__ __launch_bounds__(256) void k_convert_x(const float* __restrict__ x) {
    int i = blockIdx.x;
    int tok = g_tok[i];
    int t = threadIdx.x;
    float4 v = *(const float4*)(x + (size_t)tok * D_ + t * 4);
    __nv_bfloat16 h0 = __float2bfloat16(v.x), h1 = __float2bfloat16(v.y);
    __nv_bfloat16 h2 = __float2bfloat16(v.z), h3 = __float2bfloat16(v.w);
    __nv_bfloat16 l0 = __float2bfloat16(v.x - __bfloat162float(h0));
    __nv_bfloat16 l1 = __float2bfloat16(v.y - __bfloat162float(h1));
    __nv_bfloat16 l2 = __float2bfloat16(v.z - __bfloat162float(h2));
    __nv_bfloat16 l3 = __float2bfloat16(v.w - __bfloat162float(h3));
    size_t o = (size_t)i * D_ + t * 4;
    *(__nv_bfloat162*)(g_xh + o)     = __nv_bfloat162{h0, h1};
    *(__nv_bfloat162*)(g_xh + o + 2) = __nv_bfloat162{h2, h3};
    *(__nv_bfloat162*)(g_xl + o)     = __nv_bfloat162{l0, l1};
    *(__nv_bfloat162*)(g_xl + o + 2) = __nv_bfloat162{l2, l3};
}

__global__ __launch_bounds__(256) void k_convert_w(const float* __restrict__ W1) {
    __shared__ float s[32][33];
    int e = blockIdx.z, k0 = blockIdx.y * 32, n0 = blockIdx.x * 32;
    int tx = threadIdx.x, ty = threadIdx.y;  // (32, 8)
    const float* src = W1 + (size_t)e * D_ * H_;
#pragma unroll
    for (int r = 0; r < 4; r++)
        s[ty + 8 * r][tx] = src[(size_t)(k0 + ty + 8 * r) * H_ + n0 + tx];
    __syncthreads();
#pragma unroll
    for (int r = 0; r < 4; r++) {
        int n = n0 + ty + 8 * r, k = k0 + tx;
        float v = s[tx][ty + 8 * r];
        __nv_bfloat16 h = __float2bfloat16(v);
        __nv_bfloat16 l = __float2bfloat16(v - __bfloat162float(h));
        size_t o = ((size_t)e << 20) + (size_t)n * D_ + k;
        g_wh[o] = h;
        g_wl[o] = l;
    }
}

// ---------------- GEMM1 via mma.sync (bf16, 3-pass split) ----------------
// CTA 128x128, 8 warps (2m x 4n), warp 64x32, BK=64, double-buffered cp.async.
#define BK       64
#define ROW_B    144                       // 64 halves (128B) + 16B pad; conflict-free ldmatrix
#define TILE_SB  (128 * ROW_B)             // 18432 B per operand tile
#define STAGE_B  (4 * TILE_SB)             // Ah, Al, Bh, Bl
#define DSMEM_B  (2 * STAGE_B)             // 147456 B

__global__ __launch_bounds__(256) void k_gemm1_mma(const float* __restrict__ b1) {
    const int e   = blockIdx.z;
    const int off = g_off[e];
    const int cnt = g_off[e + 1] - off;
    const int m0  = blockIdx.y * 128;
    if (m0 >= cnt) return;
    const int n0  = blockIdx.x * 128;

    extern __shared__ char dsm[];
    __shared__ float s_bias[128];

    const int tid = threadIdx.x, wid = tid >> 5, l = tid & 31;
    const int wm = wid >> 2, wn = wid & 3;   // warp coords: 2m x 4n
    const uint32_t sbase = smem_u32(dsm);

    if (tid < 128) s_bias[tid] = b1[e * H_ + n0 + tid];

    // per-thread global/smem granule assignment: 4 granules of 16B per operand tile
    uint32_t sm_off[4];
    size_t   a_g[4], b_g[4];
#pragma unroll
    for (int j = 0; j < 4; j++) {
        int g   = tid + 256 * j;
        int row = g >> 3, kg = g & 7;
        sm_off[j] = (uint32_t)(row * ROW_B + kg * 16);
        int gm  = min(m0 + row, cnt - 1);
        a_g[j]  = (size_t)(off + gm) * D_ + kg * 8;
        b_g[j]  = ((size_t)e << 20) + (size_t)(n0 + row) * D_ + kg * 8;
    }

    float acc[4][4][4];
#pragma unroll
    for (int i = 0; i < 4; i++)
#pragma unroll
        for (int j = 0; j < 4; j++)
#pragma unroll
            for (int q = 0; q < 4; q++) acc[i][j][q] = 0.f;

    // ldmatrix per-lane invariant offsets
    const uint32_t a_loff = (uint32_t)((wm * 64 + (l & 15)) * ROW_B + ((l & 16) >> 1) * 2);
    const uint32_t b_loff = (uint32_t)((wn * 32 + (l & 7) + ((l & 16) >> 1)) * ROW_B + (l & 8) * 2);

    const int NIT = D_ / BK;   // 16

    // prologue: stage 0
#pragma unroll
    for (int j = 0; j < 4; j++) {
        uint32_t s = sbase + sm_off[j];
        cp16(s + 0 * TILE_SB, g_xh + a_g[j]);
        cp16(s + 1 * TILE_SB, g_xl + a_g[j]);
        cp16(s + 2 * TILE_SB, g_wh + b_g[j]);
        cp16(s + 3 * TILE_SB, g_wl + b_g[j]);
    }
    CP_COMMIT();

    for (int it = 0; it < NIT; ++it) {
        if (it + 1 < NIT) {
            const int kt = (it + 1) * BK;
            uint32_t st = sbase + ((it + 1) & 1) * STAGE_B;
#pragma unroll
            for (int j = 0; j < 4; j++) {
                uint32_t s = st + sm_off[j];
                cp16(s + 0 * TILE_SB, g_xh + a_g[j] + kt);
                cp16(s + 1 * TILE_SB, g_xl + a_g[j] + kt);
                cp16(s + 2 * TILE_SB, g_wh + b_g[j] + kt);
                cp16(s + 3 * TILE_SB, g_wl + b_g[j] + kt);
            }
            CP_COMMIT();
            CP_WAIT(1);
        } else {
            CP_WAIT(0);
        }
        __syncthreads();

        const uint32_t sg = sbase + (it & 1) * STAGE_B;
        const uint32_t sAh = sg + 0 * TILE_SB + a_loff;
        const uint32_t sAl = sg + 1 * TILE_SB + a_loff;
        const uint32_t sBh = sg + 2 * TILE_SB + b_loff;
        const uint32_t sBl = sg + 3 * TILE_SB + b_loff;

#pragma unroll
        for (int ks = 0; ks < BK / 16; ++ks) {
            uint32_t ah[4][4], al[4][4], bh[2][4], bl[2][4];
#pragma unroll
            for (int mt = 0; mt < 4; mt++) {
                uint32_t ao = (uint32_t)(mt * 16 * ROW_B + ks * 32);
                ldsm4(ah[mt][0], ah[mt][1], ah[mt][2], ah[mt][3], sAh + ao);
                ldsm4(al[mt][0], al[mt][1], al[mt][2], al[mt][3], sAl + ao);
            }
#pragma unroll
            for (int nt = 0; nt < 2; nt++) {
                uint32_t bo = (uint32_t)(nt * 16 * ROW_B + ks * 32);
                ldsm4(bh[nt][0], bh[nt][1], bh[nt][2], bh[nt][3], sBh + bo);
                ldsm4(bl[nt][0], bl[nt][1], bl[nt][2], bl[nt][3], sBl + bo);
            }
#pragma unroll
            for (int mt = 0; mt < 4; mt++) {
#pragma unroll
                for (int j = 0; j < 4; j++) {
                    const uint32_t* ph = &bh[j >> 1][(j & 1) * 2];
                    const uint32_t* pl = &bl[j >> 1][(j & 1) * 2];
                    mma16816(acc[mt][j], ah[mt], ph);
                    mma16816(acc[mt][j], ah[mt], pl);
                    mma16816(acc[mt][j], al[mt], ph);
                }
            }
        }
        __syncthreads();
    }

    // epilogue: bias + relu, write g_h from registers
#pragma unroll
    for (int mt = 0; mt < 4; mt++) {
        int mlo = m0 + wm * 64 + mt * 16 + (l >> 2);
        int mhi = mlo + 8;
#pragma unroll
        for (int j = 0; j < 4; j++) {
            int nb = wn * 32 + j * 8 + (l & 3) * 2;
            float bx = s_bias[nb], by = s_bias[nb + 1];
            if (mlo < cnt) {
                float2 v;
                v.x = fmaxf(acc[mt][j][0] + bx, 0.f);
                v.y = fmaxf(acc[mt][j][1] + by, 0.f);
                *(float2*)(g_h + (size_t)(off + mlo) * H_ + n0 + nb) = v;
            }
            if (mhi < cnt) {
                float2 v;
                v.x = fmaxf(acc[mt][j][2] + bx, 0.f);
                v.y = fmaxf(acc[mt][j][3] + by, 0.f);
                *(float2*)(g_h + (size_t)(off + mhi) * H_ + n0 + nb) = v;
            }
        }
    }
}

// ---------------- GEMM2 + ordinal epilogue ----------------
__global__ __launch_bounds__(256) void k_gemm2(const int* __restrict__ sidx,
                                               const float* __restrict__ W2,
                                               const float* __restrict__ b2,
                                               float* __restrict__ out, int out_size) {
    int warp = (blockIdx.x * blockDim.x + threadIdx.x) >> 5;
    int lane = threadIdx.x & 31;
    if (warp >= B_) return;
    int tok = g_tok[warp];
    int e   = get_expert(sidx, tok);

    const float* hrow = g_h + (size_t)warp * H_;
    const float* w    = W2 + (size_t)e * H_ * KM1;

    float a0 = 0.f, a1 = 0.f, a2 = 0.f, a3 = 0.f;
    for (int d = lane; d < H_; d += 32) {
        float hv = hrow[d];
        float4 wv = *(const float4*)(w + (size_t)d * 4);
        a0 += hv * wv.x; a1 += hv * wv.y; a2 += hv * wv.z; a3 += hv * wv.w;
    }
#pragma unroll
    for (int o = 16; o > 0; o >>= 1) {
        a0 += __shfl_down_sync(0xffffffffu, a0, o);
        a1 += __shfl_down_sync(0xffffffffu, a1, o);
        a2 += __shfl_down_sync(0xffffffffu, a2, o);
        a3 += __shfl_down_sync(0xffffffffu, a3, o);
    }
    if (lane == 0) {
        float lg[KM1];
        lg[0] = a0 + b2[e * KM1 + 0];
        lg[1] = a1 + b2[e * KM1 + 1];
        lg[2] = a2 + b2[e * KM1 + 2];
        lg[3] = a3 + b2[e * KM1 + 3];
        float q[KM1];
#pragma unroll
        for (int k = 0; k < KM1; k++) q[k] = 1.f / (1.f + expf(-lg[k]));
        float p[KC];
        p[0] = 1.f - q[0];
        p[1] = q[0] - q[1];
        p[2] = q[1] - q[2];
        p[3] = q[2] - q[3];
        p[4] = q[3];
        float s = 0.f;
#pragma unroll
        for (int k = 0; k < KC; k++) { p[k] = fmaxf(p[k], EPS_); s += p[k]; }
        s = fmaxf(s, EPS_);
        float inv = 1.f / s;
#pragma unroll
        for (int k = 0; k < KC; k++) p[k] *= inv;

        if (out_size >= B_ * (KM1 + KC)) {
#pragma unroll
            for (int k = 0; k < KM1; k++) out[(size_t)tok * KM1 + k] = lg[k];
#pragma unroll
            for (int k = 0; k < KC; k++)  out[(size_t)B_ * KM1 + (size_t)tok * KC + k] = p[k];
        } else if (out_size == B_ * KC) {
#pragma unroll
            for (int k = 0; k < KC; k++)  out[(size_t)tok * KC + k] = p[k];
        } else {
#pragma unroll
            for (int k = 0; k < KM1; k++) out[(size_t)tok * KM1 + k] = lg[k];
        }
    }
}

// ---------------- launch ----------------
extern "C" void kernel_launch(void* const* d_in, const int* in_sizes, int n_in,
                              void* d_out, int out_size) {
    const float* x    = (const float*)d_in[0];
    const int*   sidx = (const int*)  d_in[1];
    const float* W1   = (const float*)d_in[2];
    const float* b1   = (const float*)d_in[3];
    const float* W2   = (const float*)d_in[4];
    const float* b2   = (const float*)d_in[5];
    float*       out  = (float*)d_out;

    cudaFuncSetAttribute(k_gemm1_mma, cudaFuncAttributeMaxDynamicSharedMemorySize, DSMEM_B);

    k_convert_w<<<dim3(32, 32, 8), dim3(32, 8)>>>(W1);
    k_detect<<<1, 256>>>(sidx);
    k_count<<<B_ / 256, 256>>>(sidx);
    k_scan<<<1, 32>>>();
    k_scatter<<<B_ / 256, 256>>>(sidx);
    k_convert_x<<<B_, 256>>>(x);
    k_gemm1_mma<<<dim3(H_ / 128, B_ / 128, E_), 256, DSMEM_B>>>(b1);
    k_gemm2<<<B_ * 32 / 256, 256>>>(sidx, W2, b2, out, out_size);
}

// round 4
// speedup vs baseline: 2.7690x; 1.3704x over previous
#include <cuda_runtime.h>
#include <cuda_fp16.h>
#include <cstdint>

#define B_   8192
#define D_   1024
#define H_   1024
#define E_   8
#define KC   5
#define KM1  4
#define EPS_ 1e-8f

// ---------------- PTX helpers (sm_80-era; tcgen05 unavailable on this toolchain path) ----------------
__device__ __forceinline__ uint32_t smem_u32(const void* p) {
    uint32_t a;
    asm("{ .reg .u64 t; cvta.to.shared.u64 t, %1; cvt.u32.u64 %0, t; }" : "=r"(a) : "l"(p));
    return a;
}
__device__ __forceinline__ void cp16(uint32_t saddr, const void* g) {
    asm volatile("cp.async.cg.shared.global [%0], [%1], 16;" :: "r"(saddr), "l"(g));
}
#define CP_COMMIT() asm volatile("cp.async.commit_group;" ::: "memory")
#define CP_WAIT(N)  asm volatile("cp.async.wait_group %0;" :: "n"(N) : "memory")

__device__ __forceinline__ void ldsm4(uint32_t& r0, uint32_t& r1, uint32_t& r2, uint32_t& r3,
                                      uint32_t addr) {
    asm volatile("ldmatrix.sync.aligned.m8n8.x4.shared.b16 {%0,%1,%2,%3}, [%4];"
                 : "=r"(r0), "=r"(r1), "=r"(r2), "=r"(r3) : "r"(addr));
}
__device__ __forceinline__ void mma16816(float* c, const uint32_t* a, const uint32_t* b) {
    asm volatile(
        "mma.sync.aligned.m16n8k16.row.col.f32.f16.f16.f32 "
        "{%0,%1,%2,%3},{%4,%5,%6,%7},{%8,%9},{%0,%1,%2,%3};"
        : "+f"(c[0]), "+f"(c[1]), "+f"(c[2]), "+f"(c[3])
        : "r"(a[0]), "r"(a[1]), "r"(a[2]), "r"(a[3]), "r"(b[0]), "r"(b[1]));
}

// ---------------- scratch ----------------
__device__ int    g_off[E_ + 1];
__device__ int    g_tok[B_];
__device__ int    g_exp[B_];
__device__ int    g_is64;
__device__ __half g_xh[(size_t)B_ * D_];          // gathered x hi (fp16)
__device__ __half g_xl[(size_t)B_ * D_];          // gathered x lo (fp16)
__device__ __half g_w [(size_t)E_ * H_ * D_];     // W1^T fp16 [e][n][k]
__device__ float  g_plog[(size_t)8 * B_ * 4];     // partial logits per n-tile

// ---------------- fused routing (one block) ----------------
__global__ __launch_bounds__(1024) void k_route(const int* __restrict__ sidx) {
    __shared__ int s_any, s_cnt[E_], s_pos[E_], s_off[E_ + 1];
    const int t = threadIdx.x;
    if (t == 0) s_any = 0;
    if (t < E_) { s_cnt[t] = 0; s_pos[t] = 0; }
    __syncthreads();
    int any = 0;
    for (int i = t; i < B_ / 2; i += 1024)
        if (sidx[2 * i + 1] != 0) any = 1;
    if (any) atomicOr(&s_any, 1);
    __syncthreads();
    const int is64 = (s_any == 0) ? 1 : 0;
    if (t == 0) g_is64 = is64;

    int ev[8];
#pragma unroll
    for (int j = 0; j < 8; j++) {
        int b = t + j * 1024;
        int e = is64 ? sidx[2 * b] : sidx[b];
        ev[j] = e;
        atomicAdd(&s_cnt[e], 1);
    }
    __syncthreads();
    if (t == 0) {
        int acc = 0;
        for (int e = 0; e < E_; e++) { s_off[e] = acc; acc += s_cnt[e]; }
        s_off[E_] = acc;
    }
    __syncthreads();
    if (t <= E_) g_off[t] = s_off[t];
#pragma unroll
    for (int j = 0; j < 8; j++) {
        int b = t + j * 1024;
        int e = ev[j];
        int p = s_off[e] + atomicAdd(&s_pos[e], 1);
        g_tok[p] = b;
        g_exp[p] = e;
    }
}

// ---------------- conversions ----------------
__global__ __launch_bounds__(256) void k_convert_x(const float* __restrict__ x) {
    int i = blockIdx.x;
    int tok = g_tok[i];
    int t = threadIdx.x;
    float4 v = *(const float4*)(x + (size_t)tok * D_ + t * 4);
    __half h0 = __float2half(v.x), h1 = __float2half(v.y);
    __half h2 = __float2half(v.z), h3 = __float2half(v.w);
    __half l0 = __float2half(v.x - __half2float(h0));
    __half l1 = __float2half(v.y - __half2float(h1));
    __half l2 = __float2half(v.z - __half2float(h2));
    __half l3 = __float2half(v.w - __half2float(h3));
    size_t o = (size_t)i * D_ + t * 4;
    *(__half2*)(g_xh + o)     = __halves2half2(h0, h1);
    *(__half2*)(g_xh + o + 2) = __halves2half2(h2, h3);
    *(__half2*)(g_xl + o)     = __halves2half2(l0, l1);
    *(__half2*)(g_xl + o + 2) = __halves2half2(l2, l3);
}

__global__ __launch_bounds__(256) void k_convert_w(const float* __restrict__ W1) {
    __shared__ float s[32][33];
    int e = blockIdx.z, k0 = blockIdx.y * 32, n0 = blockIdx.x * 32;
    int tx = threadIdx.x, ty = threadIdx.y;  // (32, 8)
    const float* src = W1 + (size_t)e * D_ * H_;
#pragma unroll
    for (int r = 0; r < 4; r++)
        s[ty + 8 * r][tx] = src[(size_t)(k0 + ty + 8 * r) * H_ + n0 + tx];
    __syncthreads();
#pragma unroll
    for (int r = 0; r < 4; r++) {
        int n = n0 + ty + 8 * r, k = k0 + tx;
        g_w[((size_t)e << 20) + (size_t)n * D_ + k] = __float2half(s[tx][ty + 8 * r]);
    }
}

// ---------------- GEMM1 (fp16 2-pass) + fused GEMM2 partial epilogue ----------------
// CTA 128x128, 8 warps (2m x 4n), BK=64, double-buffered cp.async.
#define BK       64
#define ROW_B    144                       // 128B row + 16B pad
#define TILE_SB  (128 * ROW_B)             // 18432 B
#define STAGE_B  (3 * TILE_SB)             // xh, xl, w
#define DSMEM_B  (2 * STAGE_B)             // 110592 B

__global__ __launch_bounds__(256) void k_gemm1(const float* __restrict__ b1,
                                               const float* __restrict__ W2) {
    const int e   = blockIdx.z;
    const int off = g_off[e];
    const int cnt = g_off[e + 1] - off;
    const int m0  = blockIdx.y * 128;
    if (m0 >= cnt) return;
    const int bx  = blockIdx.x;       // n-tile 0..7
    const int n0  = bx * 128;

    extern __shared__ char dsm[];
    __shared__ float  s_bias[128];
    __shared__ float4 s_w2[128];
    __shared__ float  s_part[4][128][4];

    const int tid = threadIdx.x, wid = tid >> 5, l = tid & 31;
    const int wm = wid >> 2, wn = wid & 3;
    const uint32_t sbase = smem_u32(dsm);

    if (tid < 128) {
        s_bias[tid] = b1[e * H_ + n0 + tid];
        s_w2[tid]   = *(const float4*)(W2 + ((size_t)e * H_ + n0 + tid) * KM1);
    }

    uint32_t sm_off[4];
    size_t   a_g[4], b_g[4];
#pragma unroll
    for (int j = 0; j < 4; j++) {
        int g   = tid + 256 * j;
        int row = g >> 3, kg = g & 7;
        sm_off[j] = (uint32_t)(row * ROW_B + kg * 16);
        int gm  = min(m0 + row, cnt - 1);
        a_g[j]  = (size_t)(off + gm) * D_ + kg * 8;
        b_g[j]  = ((size_t)e << 20) + (size_t)(n0 + row) * D_ + kg * 8;
    }

    float acc[4][4][4];
#pragma unroll
    for (int i = 0; i < 4; i++)
#pragma unroll
        for (int j = 0; j < 4; j++)
#pragma unroll
            for (int q = 0; q < 4; q++) acc[i][j][q] = 0.f;

    const uint32_t a_loff = (uint32_t)((wm * 64 + (l & 15)) * ROW_B + ((l & 16) >> 1) * 2);
    const uint32_t b_loff = (uint32_t)((wn * 32 + (l & 7) + ((l & 16) >> 1)) * ROW_B + (l & 8) * 2);

    const int NIT = D_ / BK;   // 16

#pragma unroll
    for (int j = 0; j < 4; j++) {
        uint32_t s = sbase + sm_off[j];
        cp16(s + 0 * TILE_SB, g_xh + a_g[j]);
        cp16(s + 1 * TILE_SB, g_xl + a_g[j]);
        cp16(s + 2 * TILE_SB, g_w  + b_g[j]);
    }
    CP_COMMIT();

    for (int it = 0; it < NIT; ++it) {
        if (it + 1 < NIT) {
            const int kt = (it + 1) * BK;
            uint32_t st = sbase + ((it + 1) & 1) * STAGE_B;
#pragma unroll
            for (int j = 0; j < 4; j++) {
                uint32_t s = st + sm_off[j];
                cp16(s + 0 * TILE_SB, g_xh + a_g[j] + kt);
                cp16(s + 1 * TILE_SB, g_xl + a_g[j] + kt);
                cp16(s + 2 * TILE_SB, g_w  + b_g[j] + kt);
            }
            CP_COMMIT();
            CP_WAIT(1);
        } else {
            CP_WAIT(0);
        }
        __syncthreads();

        const uint32_t sg  = sbase + (it & 1) * STAGE_B;
        const uint32_t sAh = sg + 0 * TILE_SB + a_loff;
        const uint32_t sAl = sg + 1 * TILE_SB + a_loff;
        const uint32_t sW  = sg + 2 * TILE_SB + b_loff;

#pragma unroll
        for (int ks = 0; ks < BK / 16; ++ks) {
            uint32_t ah[4][4], al[4][4], wf[2][4];
#pragma unroll
            for (int mt = 0; mt < 4; mt++) {
                uint32_t ao = (uint32_t)(mt * 16 * ROW_B + ks * 32);
                ldsm4(ah[mt][0], ah[mt][1], ah[mt][2], ah[mt][3], sAh + ao);
                ldsm4(al[mt][0], al[mt][1], al[mt][2], al[mt][3], sAl + ao);
            }
#pragma unroll
            for (int nt = 0; nt < 2; nt++) {
                uint32_t bo = (uint32_t)(nt * 16 * ROW_B + ks * 32);
                ldsm4(wf[nt][0], wf[nt][1], wf[nt][2], wf[nt][3], sW + bo);
            }
#pragma unroll
            for (int mt = 0; mt < 4; mt++) {
#pragma unroll
                for (int j = 0; j < 4; j++) {
                    const uint32_t* pw = &wf[j >> 1][(j & 1) * 2];
                    mma16816(acc[mt][j], ah[mt], pw);
                    mma16816(acc[mt][j], al[mt], pw);
                }
            }
        }
        __syncthreads();
    }

    // ---- fused epilogue: h = relu(acc + b1); partial logits = h_slab @ W2_block ----
    float pl[4][2][4];
#pragma unroll
    for (int mt = 0; mt < 4; mt++)
#pragma unroll
        for (int g = 0; g < 2; g++)
#pragma unroll
            for (int k = 0; k < 4; k++) pl[mt][g][k] = 0.f;

#pragma unroll
    for (int mt = 0; mt < 4; mt++) {
#pragma unroll
        for (int j = 0; j < 4; j++) {
            int nb = wn * 32 + j * 8 + (l & 3) * 2;
            float4 w20 = s_w2[nb], w21 = s_w2[nb + 1];
            float bx0 = s_bias[nb], bx1 = s_bias[nb + 1];
            float h00 = fmaxf(acc[mt][j][0] + bx0, 0.f);
            float h01 = fmaxf(acc[mt][j][1] + bx1, 0.f);
            float h10 = fmaxf(acc[mt][j][2] + bx0, 0.f);
            float h11 = fmaxf(acc[mt][j][3] + bx1, 0.f);
            pl[mt][0][0] += h00 * w20.x + h01 * w21.x;
            pl[mt][0][1] += h00 * w20.y + h01 * w21.y;
            pl[mt][0][2] += h00 * w20.z + h01 * w21.z;
            pl[mt][0][3] += h00 * w20.w + h01 * w21.w;
            pl[mt][1][0] += h10 * w20.x + h11 * w21.x;
            pl[mt][1][1] += h10 * w20.y + h11 * w21.y;
            pl[mt][1][2] += h10 * w20.z + h11 * w21.z;
            pl[mt][1][3] += h10 * w20.w + h11 * w21.w;
        }
    }
    // reduce across the 4 lanes holding different n-cols of the same row
#pragma unroll
    for (int mt = 0; mt < 4; mt++)
#pragma unroll
        for (int g = 0; g < 2; g++)
#pragma unroll
            for (int k = 0; k < 4; k++) {
                float v = pl[mt][g][k];
                v += __shfl_xor_sync(0xffffffffu, v, 1);
                v += __shfl_xor_sync(0xffffffffu, v, 2);
                pl[mt][g][k] = v;
            }
    if ((l & 3) == 0) {
        int r = l >> 2;
#pragma unroll
        for (int mt = 0; mt < 4; mt++)
#pragma unroll
            for (int g = 0; g < 2; g++) {
                int row = wm * 64 + mt * 16 + r + g * 8;
#pragma unroll
                for (int k = 0; k < 4; k++) s_part[wn][row][k] = pl[mt][g][k];
            }
    }
    __syncthreads();
    if (tid < 128) {
        int m = m0 + tid;
        if (m < cnt) {
            float4 s;
            s.x = s_part[0][tid][0] + s_part[1][tid][0] + s_part[2][tid][0] + s_part[3][tid][0];
            s.y = s_part[0][tid][1] + s_part[1][tid][1] + s_part[2][tid][1] + s_part[3][tid][1];
            s.z = s_part[0][tid][2] + s_part[1][tid][2] + s_part[2][tid][2] + s_part[3][tid][2];
            s.w = s_part[0][tid][3] + s_part[1][tid][3] + s_part[2][tid][3] + s_part[3][tid][3];
            *(float4*)(g_plog + ((size_t)bx * B_ + off + m) * 4) = s;
        }
    }
}

// ---------------- finalize: sum partials + ordinal softmax ----------------
__global__ __launch_bounds__(256) void k_fin(const float* __restrict__ b2,
                                             float* __restrict__ out, int out_size) {
    int i = blockIdx.x * blockDim.x + threadIdx.x;
    if (i >= B_) return;
    float4 a = make_float4(0.f, 0.f, 0.f, 0.f);
#pragma unroll
    for (int s = 0; s < 8; s++) {
        float4 v = *(const float4*)(g_plog + ((size_t)s * B_ + i) * 4);
        a.x += v.x; a.y += v.y; a.z += v.z; a.w += v.w;
    }
    int e   = g_exp[i];
    int tok = g_tok[i];
    float lg[KM1];
    lg[0] = a.x + b2[e * KM1 + 0];
    lg[1] = a.y + b2[e * KM1 + 1];
    lg[2] = a.z + b2[e * KM1 + 2];
    lg[3] = a.w + b2[e * KM1 + 3];
    float q[KM1];
#pragma unroll
    for (int k = 0; k < KM1; k++) q[k] = 1.f / (1.f + expf(-lg[k]));
    float p[KC];
    p[0] = 1.f - q[0];
    p[1] = q[0] - q[1];
    p[2] = q[1] - q[2];
    p[3] = q[2] - q[3];
    p[4] = q[3];
    float s = 0.f;
#pragma unroll
    for (int k = 0; k < KC; k++) { p[k] = fmaxf(p[k], EPS_); s += p[k]; }
    s = fmaxf(s, EPS_);
    float inv = 1.f / s;
#pragma unroll
    for (int k = 0; k < KC; k++) p[k] *= inv;

    if (out_size >= B_ * (KM1 + KC)) {
#pragma unroll
        for (int k = 0; k < KM1; k++) out[(size_t)tok * KM1 + k] = lg[k];
#pragma unroll
        for (int k = 0; k < KC; k++)  out[(size_t)B_ * KM1 + (size_t)tok * KC + k] = p[k];
    } else if (out_size == B_ * KC) {
#pragma unroll
        for (int k = 0; k < KC; k++)  out[(size_t)tok * KC + k] = p[k];
    } else {
#pragma unroll
        for (int k = 0; k < KM1; k++) out[(size_t)tok * KM1 + k] = lg[k];
    }
}

// ---------------- launch ----------------
extern "C" void kernel_launch(void* const* d_in, const int* in_sizes, int n_in,
                              void* d_out, int out_size) {
    const float* x    = (const float*)d_in[0];
    const int*   sidx = (const int*)  d_in[1];
    const float* W1   = (const float*)d_in[2];
    const float* b1   = (const float*)d_in[3];
    const float* W2   = (const float*)d_in[4];
    const float* b2   = (const float*)d_in[5];
    float*       out  = (float*)d_out;

    cudaFuncSetAttribute(k_gemm1, cudaFuncAttributeMaxDynamicSharedMemorySize, DSMEM_B);

    k_convert_w<<<dim3(32, 32, 8), dim3(32, 8)>>>(W1);
    k_route<<<1, 1024>>>(sidx);
    k_convert_x<<<B_, 256>>>(x);
    k_gemm1<<<dim3(8, B_ / 128, E_), 256, DSMEM_B>>>(b1, W2);
    k_fin<<<B_ / 256, 256>>>(b2, out, out_size);
}

// round 5
// speedup vs baseline: 4.6060x; 1.6634x over previous
#include <cuda_runtime.h>
#include <cuda_fp16.h>
#include <cstdint>

#define B_   8192
#define D_   1024
#define H_   1024
#define E_   8
#define KC   5
#define KM1  4
#define EPS_ 1e-8f

// ---------------- PTX helpers (sm_80-era; tcgen05 unavailable on this toolchain path) ----------------
__device__ __forceinline__ uint32_t smem_u32(const void* p) {
    uint32_t a;
    asm("{ .reg .u64 t; cvta.to.shared.u64 t, %1; cvt.u32.u64 %0, t; }" : "=r"(a) : "l"(p));
    return a;
}
__device__ __forceinline__ void cp16(uint32_t saddr, const void* g) {
    asm volatile("cp.async.cg.shared.global [%0], [%1], 16;" :: "r"(saddr), "l"(g));
}
#define CP_COMMIT() asm volatile("cp.async.commit_group;" ::: "memory")
#define CP_WAIT(N)  asm volatile("cp.async.wait_group %0;" :: "n"(N) : "memory")

__device__ __forceinline__ void ldsm4(uint32_t& r0, uint32_t& r1, uint32_t& r2, uint32_t& r3,
                                      uint32_t addr) {
    asm volatile("ldmatrix.sync.aligned.m8n8.x4.shared.b16 {%0,%1,%2,%3}, [%4];"
                 : "=r"(r0), "=r"(r1), "=r"(r2), "=r"(r3) : "r"(addr));
}
__device__ __forceinline__ void mma16816(float* c, const uint32_t* a, const uint32_t* b) {
    asm volatile(
        "mma.sync.aligned.m16n8k16.row.col.f32.f16.f16.f32 "
        "{%0,%1,%2,%3},{%4,%5,%6,%7},{%8,%9},{%0,%1,%2,%3};"
        : "+f"(c[0]), "+f"(c[1]), "+f"(c[2]), "+f"(c[3])
        : "r"(a[0]), "r"(a[1]), "r"(a[2]), "r"(a[3]), "r"(b[0]), "r"(b[1]));
}

// ---------------- scratch ----------------
__device__ int    g_off[E_ + 1];
__device__ int    g_tok[B_];
__device__ int    g_exp[B_];
__device__ int    g_is64;
__device__ __half g_x[(size_t)B_ * D_];           // gathered x (fp16)
__device__ __half g_w[(size_t)E_ * H_ * D_];      // W1^T fp16 [e][n][k]
__device__ float  g_plog[(size_t)8 * B_ * 4];     // partial logits per n-tile

// ---------------- fused routing (one block) ----------------
__global__ __launch_bounds__(1024) void k_route(const int* __restrict__ sidx) {
    __shared__ int s_any, s_cnt[E_], s_pos[E_], s_off[E_ + 1];
    const int t = threadIdx.x;
    if (t == 0) s_any = 0;
    if (t < E_) { s_cnt[t] = 0; s_pos[t] = 0; }
    __syncthreads();
    int any = 0;
    for (int i = t; i < B_ / 2; i += 1024)
        if (sidx[2 * i + 1] != 0) any = 1;
    if (any) atomicOr(&s_any, 1);
    __syncthreads();
    const int is64 = (s_any == 0) ? 1 : 0;
    if (t == 0) g_is64 = is64;

    int ev[8];
#pragma unroll
    for (int j = 0; j < 8; j++) {
        int b = t + j * 1024;
        int e = is64 ? sidx[2 * b] : sidx[b];
        ev[j] = e;
        atomicAdd(&s_cnt[e], 1);
    }
    __syncthreads();
    if (t == 0) {
        int acc = 0;
        for (int e = 0; e < E_; e++) { s_off[e] = acc; acc += s_cnt[e]; }
        s_off[E_] = acc;
    }
    __syncthreads();
    if (t <= E_) g_off[t] = s_off[t];
#pragma unroll
    for (int j = 0; j < 8; j++) {
        int b = t + j * 1024;
        int e = ev[j];
        int p = s_off[e] + atomicAdd(&s_pos[e], 1);
        g_tok[p] = b;
        g_exp[p] = e;
    }
}

// ---------------- conversions ----------------
__global__ __launch_bounds__(256) void k_convert_x(const float* __restrict__ x) {
    int i = blockIdx.x;
    int tok = g_tok[i];
    int t = threadIdx.x;
    float4 v = *(const float4*)(x + (size_t)tok * D_ + t * 4);
    size_t o = (size_t)i * D_ + t * 4;
    *(__half2*)(g_x + o)     = __halves2half2(__float2half(v.x), __float2half(v.y));
    *(__half2*)(g_x + o + 2) = __halves2half2(__float2half(v.z), __float2half(v.w));
}

__global__ __launch_bounds__(256) void k_convert_w(const float* __restrict__ W1) {
    __shared__ float s[32][33];
    int e = blockIdx.z, k0 = blockIdx.y * 32, n0 = blockIdx.x * 32;
    int tx = threadIdx.x, ty = threadIdx.y;  // (32, 8)
    const float* src = W1 + (size_t)e * D_ * H_;
#pragma unroll
    for (int r = 0; r < 4; r++)
        s[ty + 8 * r][tx] = src[(size_t)(k0 + ty + 8 * r) * H_ + n0 + tx];
    __syncthreads();
#pragma unroll
    for (int r = 0; r < 4; r++) {
        int n = n0 + ty + 8 * r, k = k0 + tx;
        g_w[((size_t)e << 20) + (size_t)n * D_ + k] = __float2half(s[tx][ty + 8 * r]);
    }
}

// ---------------- GEMM1 (fp16 single-pass) + fused GEMM2 partial epilogue ----------------
// CTA 128x128, 8 warps (2m x 4n), BK=64, double-buffered cp.async, 2 CTAs/SM.
#define BK       64
#define ROW_B    144                       // 128B row + 16B pad
#define TILE_SB  (128 * ROW_B)             // 18432 B
#define STAGE_B  (2 * TILE_SB)             // x, w
#define DSMEM_B  (2 * STAGE_B)             // 73728 B

__global__ __launch_bounds__(256, 2) void k_gemm1(const float* __restrict__ b1,
                                                  const float* __restrict__ W2) {
    const int e   = blockIdx.z;
    const int off = g_off[e];
    const int cnt = g_off[e + 1] - off;
    const int m0  = blockIdx.y * 128;
    if (m0 >= cnt) return;
    const int bx  = blockIdx.x;       // n-tile 0..7
    const int n0  = bx * 128;

    extern __shared__ char dsm[];
    __shared__ float  s_bias[128];
    __shared__ float4 s_w2[128];
    __shared__ float  s_part[4][128][4];

    const int tid = threadIdx.x, wid = tid >> 5, l = tid & 31;
    const int wm = wid >> 2, wn = wid & 3;
    const uint32_t sbase = smem_u32(dsm);

    if (tid < 128) {
        s_bias[tid] = b1[e * H_ + n0 + tid];
        s_w2[tid]   = *(const float4*)(W2 + ((size_t)e * H_ + n0 + tid) * KM1);
    }

    uint32_t sm_off[4];
    size_t   a_g[4], b_g[4];
#pragma unroll
    for (int j = 0; j < 4; j++) {
        int g   = tid + 256 * j;
        int row = g >> 3, kg = g & 7;
        sm_off[j] = (uint32_t)(row * ROW_B + kg * 16);
        int gm  = min(m0 + row, cnt - 1);
        a_g[j]  = (size_t)(off + gm) * D_ + kg * 8;
        b_g[j]  = ((size_t)e << 20) + (size_t)(n0 + row) * D_ + kg * 8;
    }

    float acc[4][4][4];
#pragma unroll
    for (int i = 0; i < 4; i++)
#pragma unroll
        for (int j = 0; j < 4; j++)
#pragma unroll
            for (int q = 0; q < 4; q++) acc[i][j][q] = 0.f;

    const uint32_t a_loff = (uint32_t)((wm * 64 + (l & 15)) * ROW_B + ((l & 16) >> 1) * 2);
    const uint32_t b_loff = (uint32_t)((wn * 32 + (l & 7) + ((l & 16) >> 1)) * ROW_B + (l & 8) * 2);

    const int NIT = D_ / BK;   // 16

#pragma unroll
    for (int j = 0; j < 4; j++) {
        uint32_t s = sbase + sm_off[j];
        cp16(s + 0 * TILE_SB, g_x + a_g[j]);
        cp16(s + 1 * TILE_SB, g_w + b_g[j]);
    }
    CP_COMMIT();

    for (int it = 0; it < NIT; ++it) {
        if (it + 1 < NIT) {
            const int kt = (it + 1) * BK;
            uint32_t st = sbase + ((it + 1) & 1) * STAGE_B;
#pragma unroll
            for (int j = 0; j < 4; j++) {
                uint32_t s = st + sm_off[j];
                cp16(s + 0 * TILE_SB, g_x + a_g[j] + kt);
                cp16(s + 1 * TILE_SB, g_w + b_g[j] + kt);
            }
            CP_COMMIT();
            CP_WAIT(1);
        } else {
            CP_WAIT(0);
        }
        __syncthreads();

        const uint32_t sg = sbase + (it & 1) * STAGE_B;
        const uint32_t sA = sg + 0 * TILE_SB + a_loff;
        const uint32_t sW = sg + 1 * TILE_SB + b_loff;

#pragma unroll
        for (int ks = 0; ks < BK / 16; ++ks) {
            uint32_t ar[4][4], wf[2][4];
#pragma unroll
            for (int mt = 0; mt < 4; mt++) {
                uint32_t ao = (uint32_t)(mt * 16 * ROW_B + ks * 32);
                ldsm4(ar[mt][0], ar[mt][1], ar[mt][2], ar[mt][3], sA + ao);
            }
#pragma unroll
            for (int nt = 0; nt < 2; nt++) {
                uint32_t bo = (uint32_t)(nt * 16 * ROW_B + ks * 32);
                ldsm4(wf[nt][0], wf[nt][1], wf[nt][2], wf[nt][3], sW + bo);
            }
#pragma unroll
            for (int mt = 0; mt < 4; mt++) {
#pragma unroll
                for (int j = 0; j < 4; j++) {
                    mma16816(acc[mt][j], ar[mt], &wf[j >> 1][(j & 1) * 2]);
                }
            }
        }
        __syncthreads();
    }

    // ---- fused epilogue: h = relu(acc + b1); partial logits = h_slab @ W2_block ----
    float pl[4][2][4];
#pragma unroll
    for (int mt = 0; mt < 4; mt++)
#pragma unroll
        for (int g = 0; g < 2; g++)
#pragma unroll
            for (int k = 0; k < 4; k++) pl[mt][g][k] = 0.f;

#pragma unroll
    for (int mt = 0; mt < 4; mt++) {
#pragma unroll
        for (int j = 0; j < 4; j++) {
            int nb = wn * 32 + j * 8 + (l & 3) * 2;
            float4 w20 = s_w2[nb], w21 = s_w2[nb + 1];
            float bx0 = s_bias[nb], bx1 = s_bias[nb + 1];
            float h00 = fmaxf(acc[mt][j][0] + bx0, 0.f);
            float h01 = fmaxf(acc[mt][j][1] + bx1, 0.f);
            float h10 = fmaxf(acc[mt][j][2] + bx0, 0.f);
            float h11 = fmaxf(acc[mt][j][3] + bx1, 0.f);
            pl[mt][0][0] += h00 * w20.x + h01 * w21.x;
            pl[mt][0][1] += h00 * w20.y + h01 * w21.y;
            pl[mt][0][2] += h00 * w20.z + h01 * w21.z;
            pl[mt][0][3] += h00 * w20.w + h01 * w21.w;
            pl[mt][1][0] += h10 * w20.x + h11 * w21.x;
            pl[mt][1][1] += h10 * w20.y + h11 * w21.y;
            pl[mt][1][2] += h10 * w20.z + h11 * w21.z;
            pl[mt][1][3] += h10 * w20.w + h11 * w21.w;
        }
    }
#pragma unroll
    for (int mt = 0; mt < 4; mt++)
#pragma unroll
        for (int g = 0; g < 2; g++)
#pragma unroll
            for (int k = 0; k < 4; k++) {
                float v = pl[mt][g][k];
                v += __shfl_xor_sync(0xffffffffu, v, 1);
                v += __shfl_xor_sync(0xffffffffu, v, 2);
                pl[mt][g][k] = v;
            }
    if ((l & 3) == 0) {
        int r = l >> 2;
#pragma unroll
        for (int mt = 0; mt < 4; mt++)
#pragma unroll
            for (int g = 0; g < 2; g++) {
                int row = wm * 64 + mt * 16 + r + g * 8;
#pragma unroll
                for (int k = 0; k < 4; k++) s_part[wn][row][k] = pl[mt][g][k];
            }
    }
    __syncthreads();
    if (tid < 128) {
        int m = m0 + tid;
        if (m < cnt) {
            float4 s;
            s.x = s_part[0][tid][0] + s_part[1][tid][0] + s_part[2][tid][0] + s_part[3][tid][0];
            s.y = s_part[0][tid][1] + s_part[1][tid][1] + s_part[2][tid][1] + s_part[3][tid][1];
            s.z = s_part[0][tid][2] + s_part[1][tid][2] + s_part[2][tid][2] + s_part[3][tid][2];
            s.w = s_part[0][tid][3] + s_part[1][tid][3] + s_part[2][tid][3] + s_part[3][tid][3];
            *(float4*)(g_plog + ((size_t)bx * B_ + off + m) * 4) = s;
        }
    }
}

// ---------------- finalize: sum partials + ordinal softmax ----------------
__global__ __launch_bounds__(256) void k_fin(const float* __restrict__ b2,
                                             float* __restrict__ out, int out_size) {
    int i = blockIdx.x * blockDim.x + threadIdx.x;
    if (i >= B_) return;
    float4 a = make_float4(0.f, 0.f, 0.f, 0.f);
#pragma unroll
    for (int s = 0; s < 8; s++) {
        float4 v = *(const float4*)(g_plog + ((size_t)s * B_ + i) * 4);
        a.x += v.x; a.y += v.y; a.z += v.z; a.w += v.w;
    }
    int e   = g_exp[i];
    int tok = g_tok[i];
    float lg[KM1];
    lg[0] = a.x + b2[e * KM1 + 0];
    lg[1] = a.y + b2[e * KM1 + 1];
    lg[2] = a.z + b2[e * KM1 + 2];
    lg[3] = a.w + b2[e * KM1 + 3];
    float q[KM1];
#pragma unroll
    for (int k = 0; k < KM1; k++) q[k] = 1.f / (1.f + expf(-lg[k]));
    float p[KC];
    p[0] = 1.f - q[0];
    p[1] = q[0] - q[1];
    p[2] = q[1] - q[2];
    p[3] = q[2] - q[3];
    p[4] = q[3];
    float s = 0.f;
#pragma unroll
    for (int k = 0; k < KC; k++) { p[k] = fmaxf(p[k], EPS_); s += p[k]; }
    s = fmaxf(s, EPS_);
    float inv = 1.f / s;
#pragma unroll
    for (int k = 0; k < KC; k++) p[k] *= inv;

    if (out_size >= B_ * (KM1 + KC)) {
#pragma unroll
        for (int k = 0; k < KM1; k++) out[(size_t)tok * KM1 + k] = lg[k];
#pragma unroll
        for (int k = 0; k < KC; k++)  out[(size_t)B_ * KM1 + (size_t)tok * KC + k] = p[k];
    } else if (out_size == B_ * KC) {
#pragma unroll
        for (int k = 0; k < KC; k++)  out[(size_t)tok * KC + k] = p[k];
    } else {
#pragma unroll
        for (int k = 0; k < KM1; k++) out[(size_t)tok * KM1 + k] = lg[k];
    }
}

// ---------------- launch ----------------
extern "C" void kernel_launch(void* const* d_in, const int* in_sizes, int n_in,
                              void* d_out, int out_size) {
    const float* x    = (const float*)d_in[0];
    const int*   sidx = (const int*)  d_in[1];
    const float* W1   = (const float*)d_in[2];
    const float* b1   = (const float*)d_in[3];
    const float* W2   = (const float*)d_in[4];
    const float* b2   = (const float*)d_in[5];
    float*       out  = (float*)d_out;

    cudaFuncSetAttribute(k_gemm1, cudaFuncAttributeMaxDynamicSharedMemorySize, DSMEM_B);

    k_convert_w<<<dim3(32, 32, 8), dim3(32, 8)>>>(W1);
    k_route<<<1, 1024>>>(sidx);
    k_convert_x<<<B_, 256>>>(x);
    k_gemm1<<<dim3(8, B_ / 128, E_), 256, DSMEM_B>>>(b1, W2);
    k_fin<<<B_ / 256, 256>>>(b2, out, out_size);
}

// round 6
// speedup vs baseline: 4.8659x; 1.0564x over previous
#include <cuda_runtime.h>
#include <cuda_fp16.h>
#include <cstdint>

#define B_   8192
#define D_   1024
#define H_   1024
#define E_   8
#define KC   5
#define KM1  4
#define EPS_ 1e-8f

// ---------------- PTX helpers (sm_80-era; tcgen05 unavailable on this toolchain path) ----------------
__device__ __forceinline__ uint32_t smem_u32(const void* p) {
    uint32_t a;
    asm("{ .reg .u64 t; cvta.to.shared.u64 t, %1; cvt.u32.u64 %0, t; }" : "=r"(a) : "l"(p));
    return a;
}
__device__ __forceinline__ void cp16(uint32_t saddr, const void* g) {
    asm volatile("cp.async.cg.shared.global [%0], [%1], 16;" :: "r"(saddr), "l"(g));
}
#define CP_COMMIT() asm volatile("cp.async.commit_group;" ::: "memory")
#define CP_WAIT(N)  asm volatile("cp.async.wait_group %0;" :: "n"(N) : "memory")

__device__ __forceinline__ void ldsm4(uint32_t& r0, uint32_t& r1, uint32_t& r2, uint32_t& r3,
                                      uint32_t addr) {
    asm volatile("ldmatrix.sync.aligned.m8n8.x4.shared.b16 {%0,%1,%2,%3}, [%4];"
                 : "=r"(r0), "=r"(r1), "=r"(r2), "=r"(r3) : "r"(addr));
}
__device__ __forceinline__ void mma16816(float* c, const uint32_t* a, const uint32_t* b) {
    asm volatile(
        "mma.sync.aligned.m16n8k16.row.col.f32.f16.f16.f32 "
        "{%0,%1,%2,%3},{%4,%5,%6,%7},{%8,%9},{%0,%1,%2,%3};"
        : "+f"(c[0]), "+f"(c[1]), "+f"(c[2]), "+f"(c[3])
        : "r"(a[0]), "r"(a[1]), "r"(a[2]), "r"(a[3]), "r"(b[0]), "r"(b[1]));
}

// ---------------- scratch ----------------
__device__ int    g_off[E_ + 1];
__device__ int    g_tok[B_];
__device__ int    g_exp[B_];
__device__ int    g_is64;
__device__ __half g_x[(size_t)B_ * D_];           // x fp16, TOKEN order (no gather)
__device__ __half g_w[(size_t)E_ * H_ * D_];      // W1^T fp16 [e][n][k]
__device__ float  g_plog[(size_t)8 * B_ * 4];     // partial logits per n-tile

// ---------------- fused routing (one block) ----------------
__global__ __launch_bounds__(1024) void k_route(const int* __restrict__ sidx) {
    __shared__ int s_any, s_cnt[E_], s_pos[E_], s_off[E_ + 1];
    const int t = threadIdx.x;
    if (t == 0) s_any = 0;
    if (t < E_) { s_cnt[t] = 0; s_pos[t] = 0; }
    __syncthreads();
    int any = 0;
    for (int i = t; i < B_ / 2; i += 1024)
        if (sidx[2 * i + 1] != 0) any = 1;
    if (any) atomicOr(&s_any, 1);
    __syncthreads();
    const int is64 = (s_any == 0) ? 1 : 0;
    if (t == 0) g_is64 = is64;

    int ev[8];
#pragma unroll
    for (int j = 0; j < 8; j++) {
        int b = t + j * 1024;
        int e = is64 ? sidx[2 * b] : sidx[b];
        ev[j] = e;
        atomicAdd(&s_cnt[e], 1);
    }
    __syncthreads();
    if (t == 0) {
        int acc = 0;
        for (int e = 0; e < E_; e++) { s_off[e] = acc; acc += s_cnt[e]; }
        s_off[E_] = acc;
    }
    __syncthreads();
    if (t <= E_) g_off[t] = s_off[t];
#pragma unroll
    for (int j = 0; j < 8; j++) {
        int b = t + j * 1024;
        int e = ev[j];
        int p = s_off[e] + atomicAdd(&s_pos[e], 1);
        g_tok[p] = b;
        g_exp[p] = e;
    }
}

// ---------------- conversions (both independent of routing) ----------------
__global__ __launch_bounds__(256) void k_convert_x(const float* __restrict__ x) {
    size_t i = (size_t)blockIdx.x * 1024 + threadIdx.x * 4;
    float4 v = *(const float4*)(x + i);
    *(__half2*)(g_x + i)     = __halves2half2(__float2half(v.x), __float2half(v.y));
    *(__half2*)(g_x + i + 2) = __halves2half2(__float2half(v.z), __float2half(v.w));
}

__global__ __launch_bounds__(256) void k_convert_w(const float* __restrict__ W1) {
    __shared__ float s[32][33];
    int e = blockIdx.z, k0 = blockIdx.y * 32, n0 = blockIdx.x * 32;
    int tx = threadIdx.x, ty = threadIdx.y;  // (32, 8)
    const float* src = W1 + (size_t)e * D_ * H_;
#pragma unroll
    for (int r = 0; r < 4; r++)
        s[ty + 8 * r][tx] = src[(size_t)(k0 + ty + 8 * r) * H_ + n0 + tx];
    __syncthreads();
#pragma unroll
    for (int r = 0; r < 4; r++) {
        int n = n0 + ty + 8 * r, k = k0 + tx;
        g_w[((size_t)e << 20) + (size_t)n * D_ + k] = __float2half(s[tx][ty + 8 * r]);
    }
}

// ---------------- GEMM1 (fp16 single-pass) + fused GEMM2 partial epilogue ----------------
// CTA 128x128, 8 warps (2m x 4n), BK=64, double-buffered cp.async, 2 CTAs/SM.
// A rows resolved through g_tok (gather folded into the GEMM loads).
#define BK       64
#define ROW_B    144                       // 128B row + 16B pad
#define TILE_SB  (128 * ROW_B)             // 18432 B
#define STAGE_B  (2 * TILE_SB)             // x, w
#define DSMEM_B  (2 * STAGE_B)             // 73728 B

__global__ __launch_bounds__(256, 2) void k_gemm1(const float* __restrict__ b1,
                                                  const float* __restrict__ W2) {
    const int e   = blockIdx.z;
    const int off = g_off[e];
    const int cnt = g_off[e + 1] - off;
    const int m0  = blockIdx.y * 128;
    if (m0 >= cnt) return;
    const int bx  = blockIdx.x;       // n-tile 0..7
    const int n0  = bx * 128;

    extern __shared__ char dsm[];
    __shared__ float  s_bias[128];
    __shared__ float4 s_w2[128];
    __shared__ float  s_part[4][128][4];

    const int tid = threadIdx.x, wid = tid >> 5, l = tid & 31;
    const int wm = wid >> 2, wn = wid & 3;
    const uint32_t sbase = smem_u32(dsm);

    if (tid < 128) {
        s_bias[tid] = b1[e * H_ + n0 + tid];
        s_w2[tid]   = *(const float4*)(W2 + ((size_t)e * H_ + n0 + tid) * KM1);
    }

    uint32_t sm_off[4];
    size_t   a_g[4], b_g[4];
#pragma unroll
    for (int j = 0; j < 4; j++) {
        int g   = tid + 256 * j;
        int row = g >> 3, kg = g & 7;
        sm_off[j] = (uint32_t)(row * ROW_B + kg * 16);
        int gm  = min(m0 + row, cnt - 1);
        int tok = g_tok[off + gm];
        a_g[j]  = (size_t)tok * D_ + kg * 8;
        b_g[j]  = ((size_t)e << 20) + (size_t)(n0 + row) * D_ + kg * 8;
    }

    float acc[4][4][4];
#pragma unroll
    for (int i = 0; i < 4; i++)
#pragma unroll
        for (int j = 0; j < 4; j++)
#pragma unroll
            for (int q = 0; q < 4; q++) acc[i][j][q] = 0.f;

    const uint32_t a_loff = (uint32_t)((wm * 64 + (l & 15)) * ROW_B + ((l & 16) >> 1) * 2);
    const uint32_t b_loff = (uint32_t)((wn * 32 + (l & 7) + ((l & 16) >> 1)) * ROW_B + (l & 8) * 2);

    const int NIT = D_ / BK;   // 16

#pragma unroll
    for (int j = 0; j < 4; j++) {
        uint32_t s = sbase + sm_off[j];
        cp16(s + 0 * TILE_SB, g_x + a_g[j]);
        cp16(s + 1 * TILE_SB, g_w + b_g[j]);
    }
    CP_COMMIT();

    for (int it = 0; it < NIT; ++it) {
        if (it + 1 < NIT) {
            const int kt = (it + 1) * BK;
            uint32_t st = sbase + ((it + 1) & 1) * STAGE_B;
#pragma unroll
            for (int j = 0; j < 4; j++) {
                uint32_t s = st + sm_off[j];
                cp16(s + 0 * TILE_SB, g_x + a_g[j] + kt);
                cp16(s + 1 * TILE_SB, g_w + b_g[j] + kt);
            }
            CP_COMMIT();
            CP_WAIT(1);
        } else {
            CP_WAIT(0);
        }
        __syncthreads();

        const uint32_t sg = sbase + (it & 1) * STAGE_B;
        const uint32_t sA = sg + 0 * TILE_SB + a_loff;
        const uint32_t sW = sg + 1 * TILE_SB + b_loff;

#pragma unroll
        for (int ks = 0; ks < BK / 16; ++ks) {
            uint32_t ar[4][4], wf[2][4];
#pragma unroll
            for (int mt = 0; mt < 4; mt++) {
                uint32_t ao = (uint32_t)(mt * 16 * ROW_B + ks * 32);
                ldsm4(ar[mt][0], ar[mt][1], ar[mt][2], ar[mt][3], sA + ao);
            }
#pragma unroll
            for (int nt = 0; nt < 2; nt++) {
                uint32_t bo = (uint32_t)(nt * 16 * ROW_B + ks * 32);
                ldsm4(wf[nt][0], wf[nt][1], wf[nt][2], wf[nt][3], sW + bo);
            }
#pragma unroll
            for (int mt = 0; mt < 4; mt++) {
#pragma unroll
                for (int j = 0; j < 4; j++) {
                    mma16816(acc[mt][j], ar[mt], &wf[j >> 1][(j & 1) * 2]);
                }
            }
        }
        __syncthreads();
    }

    // ---- fused epilogue: h = relu(acc + b1); partial logits = h_slab @ W2_block ----
    float pl[4][2][4];
#pragma unroll
    for (int mt = 0; mt < 4; mt++)
#pragma unroll
        for (int g = 0; g < 2; g++)
#pragma unroll
            for (int k = 0; k < 4; k++) pl[mt][g][k] = 0.f;

#pragma unroll
    for (int mt = 0; mt < 4; mt++) {
#pragma unroll
        for (int j = 0; j < 4; j++) {
            int nb = wn * 32 + j * 8 + (l & 3) * 2;
            float4 w20 = s_w2[nb], w21 = s_w2[nb + 1];
            float bx0 = s_bias[nb], bx1 = s_bias[nb + 1];
            float h00 = fmaxf(acc[mt][j][0] + bx0, 0.f);
            float h01 = fmaxf(acc[mt][j][1] + bx1, 0.f);
            float h10 = fmaxf(acc[mt][j][2] + bx0, 0.f);
            float h11 = fmaxf(acc[mt][j][3] + bx1, 0.f);
            pl[mt][0][0] += h00 * w20.x + h01 * w21.x;
            pl[mt][0][1] += h00 * w20.y + h01 * w21.y;
            pl[mt][0][2] += h00 * w20.z + h01 * w21.z;
            pl[mt][0][3] += h00 * w20.w + h01 * w21.w;
            pl[mt][1][0] += h10 * w20.x + h11 * w21.x;
            pl[mt][1][1] += h10 * w20.y + h11 * w21.y;
            pl[mt][1][2] += h10 * w20.z + h11 * w21.z;
            pl[mt][1][3] += h10 * w20.w + h11 * w21.w;
        }
    }
#pragma unroll
    for (int mt = 0; mt < 4; mt++)
#pragma unroll
        for (int g = 0; g < 2; g++)
#pragma unroll
            for (int k = 0; k < 4; k++) {
                float v = pl[mt][g][k];
                v += __shfl_xor_sync(0xffffffffu, v, 1);
                v += __shfl_xor_sync(0xffffffffu, v, 2);
                pl[mt][g][k] = v;
            }
    if ((l & 3) == 0) {
        int r = l >> 2;
#pragma unroll
        for (int mt = 0; mt < 4; mt++)
#pragma unroll
            for (int g = 0; g < 2; g++) {
                int row = wm * 64 + mt * 16 + r + g * 8;
#pragma unroll
                for (int k = 0; k < 4; k++) s_part[wn][row][k] = pl[mt][g][k];
            }
    }
    __syncthreads();
    if (tid < 128) {
        int m = m0 + tid;
        if (m < cnt) {
            float4 s;
            s.x = s_part[0][tid][0] + s_part[1][tid][0] + s_part[2][tid][0] + s_part[3][tid][0];
            s.y = s_part[0][tid][1] + s_part[1][tid][1] + s_part[2][tid][1] + s_part[3][tid][1];
            s.z = s_part[0][tid][2] + s_part[1][tid][2] + s_part[2][tid][2] + s_part[3][tid][2];
            s.w = s_part[0][tid][3] + s_part[1][tid][3] + s_part[2][tid][3] + s_part[3][tid][3];
            *(float4*)(g_plog + ((size_t)bx * B_ + off + m) * 4) = s;
        }
    }
}

// ---------------- finalize: sum partials + ordinal softmax ----------------
__global__ __launch_bounds__(256) void k_fin(const float* __restrict__ b2,
                                             float* __restrict__ out, int out_size) {
    int i = blockIdx.x * blockDim.x + threadIdx.x;
    if (i >= B_) return;
    float4 a = make_float4(0.f, 0.f, 0.f, 0.f);
#pragma unroll
    for (int s = 0; s < 8; s++) {
        float4 v = *(const float4*)(g_plog + ((size_t)s * B_ + i) * 4);
        a.x += v.x; a.y += v.y; a.z += v.z; a.w += v.w;
    }
    int e   = g_exp[i];
    int tok = g_tok[i];
    float lg[KM1];
    lg[0] = a.x + b2[e * KM1 + 0];
    lg[1] = a.y + b2[e * KM1 + 1];
    lg[2] = a.z + b2[e * KM1 + 2];
    lg[3] = a.w + b2[e * KM1 + 3];
    float q[KM1];
#pragma unroll
    for (int k = 0; k < KM1; k++) q[k] = 1.f / (1.f + expf(-lg[k]));
    float p[KC];
    p[0] = 1.f - q[0];
    p[1] = q[0] - q[1];
    p[2] = q[1] - q[2];
    p[3] = q[2] - q[3];
    p[4] = q[3];
    float s = 0.f;
#pragma unroll
    for (int k = 0; k < KC; k++) { p[k] = fmaxf(p[k], EPS_); s += p[k]; }
    s = fmaxf(s, EPS_);
    float inv = 1.f / s;
#pragma unroll
    for (int k = 0; k < KC; k++) p[k] *= inv;

    if (out_size >= B_ * (KM1 + KC)) {
#pragma unroll
        for (int k = 0; k < KM1; k++) out[(size_t)tok * KM1 + k] = lg[k];
#pragma unroll
        for (int k = 0; k < KC; k++)  out[(size_t)B_ * KM1 + (size_t)tok * KC + k] = p[k];
    } else if (out_size == B_ * KC) {
#pragma unroll
        for (int k = 0; k < KC; k++)  out[(size_t)tok * KC + k] = p[k];
    } else {
#pragma unroll
        for (int k = 0; k < KM1; k++) out[(size_t)tok * KM1 + k] = lg[k];
    }
}

// ---------------- launch (fork-join graph: route || convert_w || convert_x) ----------------
extern "C" void kernel_launch(void* const* d_in, const int* in_sizes, int n_in,
                              void* d_out, int out_size) {
    const float* x    = (const float*)d_in[0];
    const int*   sidx = (const int*)  d_in[1];
    const float* W1   = (const float*)d_in[2];
    const float* b1   = (const float*)d_in[3];
    const float* W2   = (const float*)d_in[4];
    const float* b2   = (const float*)d_in[5];
    float*       out  = (float*)d_out;

    // host-side stream/event objects, created once (no device memory involved)
    static cudaStream_t sA = nullptr, sB = nullptr;
    static cudaEvent_t  evR = nullptr, evA = nullptr, evB = nullptr;
    static bool attr_set = false;
    if (!sA) {
        cudaStreamCreateWithFlags(&sA, cudaStreamNonBlocking);
        cudaStreamCreateWithFlags(&sB, cudaStreamNonBlocking);
        cudaEventCreateWithFlags(&evR, cudaEventDisableTiming);
        cudaEventCreateWithFlags(&evA, cudaEventDisableTiming);
        cudaEventCreateWithFlags(&evB, cudaEventDisableTiming);
    }
    if (!attr_set) {
        cudaFuncSetAttribute(k_gemm1, cudaFuncAttributeMaxDynamicSharedMemorySize, DSMEM_B);
        attr_set = true;
    }

    // fork
    cudaEventRecord(evR, 0);
    cudaStreamWaitEvent(sA, evR, 0);
    cudaStreamWaitEvent(sB, evR, 0);

    k_route<<<1, 1024>>>(sidx);                                  // stream 0
    k_convert_w<<<dim3(32, 32, 8), dim3(32, 8), 0, sA>>>(W1);    // stream A
    k_convert_x<<<B_ * D_ / 1024, 256, 0, sB>>>(x);              // stream B

    // join
    cudaEventRecord(evA, sA);
    cudaEventRecord(evB, sB);
    cudaStreamWaitEvent(0, evA, 0);
    cudaStreamWaitEvent(0, evB, 0);

    k_gemm1<<<dim3(8, B_ / 128, E_), 256, DSMEM_B>>>(b1, W2);
    k_fin<<<B_ / 256, 256>>>(b2, out, out_size);
}